// round 2
// baseline (speedup 1.0000x reference)
#include <cuda_runtime.h>
#include <math.h>

#define T_LEN 160
#define B_SZ  640
#define IN_F  40
#define H_SZ  256
#define G_SZ  1024
#define N_SPK 64
#define M_UTT 10
#define KC    32

// ---------------- device scratch (static globals; no runtime alloc) ----------
static __device__ float g_Xg[(size_t)T_LEN * B_SZ * G_SZ];     // 419 MB: precomputed input gates
static __device__ float g_hseq[(size_t)T_LEN * B_SZ * H_SZ];   // 105 MB: h sequence (also the recurrence buffer)
static __device__ float g_c[B_SZ * H_SZ];                      // cell state
static __device__ float g_E1[B_SZ * H_SZ];
static __device__ float g_En[B_SZ * H_SZ];
static __device__ float g_C[N_SPK * H_SZ];
static __device__ float g_Cn[N_SPK * H_SZ];
static __device__ float g_d[B_SZ];

// ---------------- helpers ---------------------------------------------------
__device__ __forceinline__ float block_sum(float v, float* sh) {
    int tid = threadIdx.x;
    #pragma unroll
    for (int o = 16; o > 0; o >>= 1) v += __shfl_down_sync(0xffffffffu, v, o);
    if ((tid & 31) == 0) sh[tid >> 5] = v;
    __syncthreads();
    int nw = blockDim.x >> 5;
    float r = (tid < nw) ? sh[tid] : 0.f;
    if (tid < 32) {
        #pragma unroll
        for (int o = 16; o > 0; o >>= 1) r += __shfl_down_sync(0xffffffffu, r, o);
        if (tid == 0) sh[0] = r;
    }
    __syncthreads();
    float out = sh[0];
    __syncthreads();
    return out;
}

__device__ __forceinline__ float sigf(float x) { return 1.f / (1.f + __expf(-x)); }

// ---------------- init ------------------------------------------------------
__global__ void zero_c_kernel() {
    g_c[blockIdx.x * H_SZ + threadIdx.x] = 0.f;
}

// ---------------- bulk input GEMM: Xg = A @ Wih^T + (bih + bhh) -------------
// A (mode 0): sequences [B, T, IN], logical row = t*B + b
// A (mode 1): g_hseq [T*B, H]
// W: [1024, K] row-major. Output g_Xg [T*B, 1024].
// Block tile 64 rows x 64 cols, 128 threads, micro 4x8.
__global__ void bulk_gemm_kernel(const float* __restrict__ A,
                                 const float* __restrict__ W,
                                 const float* __restrict__ bih,
                                 const float* __restrict__ bhh,
                                 int K, int mode)
{
    __shared__ float As[64][KC + 1];
    __shared__ float Bs[64][KC + 1];

    const int row0 = blockIdx.y * 64;
    const int col0 = blockIdx.x * 64;
    const int tid  = threadIdx.x;          // 128
    const int tx   = tid & 7;              // col thread (interleaved cols tx + 8*c)
    const int ty   = tid >> 3;             // 0..15, rows ty*4..+3

    float acc[4][8];
    #pragma unroll
    for (int r = 0; r < 4; r++)
        #pragma unroll
        for (int c = 0; c < 8; c++) acc[r][c] = 0.f;

    const float* src = (mode == 0) ? A : g_hseq;
    const int nk = (K + KC - 1) / KC;

    for (int kc = 0; kc < nk; kc++) {
        const int kbase = kc * KC;
        // load A tile: 64 x 32 = 2048 elems
        for (int idx = tid; idx < 64 * KC; idx += 128) {
            int r = idx >> 5, kk = idx & 31;
            int k = kbase + kk;
            float v = 0.f;
            if (k < K) {
                int row = row0 + r;
                if (mode == 0) {
                    int t = row / B_SZ;
                    int b = row - t * B_SZ;
                    v = src[(size_t)b * (T_LEN * IN_F) + (size_t)t * IN_F + k];
                } else {
                    v = src[(size_t)row * K + k];
                }
            }
            As[r][kk] = v;
        }
        // load W tile: 64 x 32
        for (int idx = tid; idx < 64 * KC; idx += 128) {
            int r = idx >> 5, kk = idx & 31;
            int k = kbase + kk;
            Bs[r][kk] = (k < K) ? W[(size_t)(col0 + r) * K + k] : 0.f;
        }
        __syncthreads();

        #pragma unroll
        for (int kk = 0; kk < KC; kk++) {
            float a[4], w[8];
            #pragma unroll
            for (int r = 0; r < 4; r++) a[r] = As[ty * 4 + r][kk];
            #pragma unroll
            for (int c = 0; c < 8; c++) w[c] = Bs[tx + c * 8][kk];
            #pragma unroll
            for (int r = 0; r < 4; r++)
                #pragma unroll
                for (int c = 0; c < 8; c++) acc[r][c] += a[r] * w[c];
        }
        __syncthreads();
    }

    #pragma unroll
    for (int r = 0; r < 4; r++) {
        int row = row0 + ty * 4 + r;
        #pragma unroll
        for (int c = 0; c < 8; c++) {
            int col = col0 + tx + c * 8;
            g_Xg[(size_t)row * G_SZ + col] = acc[r][c] + bih[col] + bhh[col];
        }
    }
}

// ---------------- fused LSTM step -------------------------------------------
// One launch per timestep. Computes g = h_{t-1} @ Whh^T + Xg[t], applies the
// LSTM cell + packed-sequence mask, writes h into g_hseq[t] and updates g_c.
// Block: 64 batch rows x 16 h-dims (x 4 gates = 64 gate cols). 128 threads.
// Grid: (H/16, B/64) = (16, 10).
__global__ void lstm_step_kernel(const float* __restrict__ Whh,
                                 const int* __restrict__ lens,
                                 int t)
{
    __shared__ float hs[64][KC + 1];
    __shared__ float ws[4][16][KC + 1];

    const int b0 = blockIdx.y * 64;
    const int n0 = blockIdx.x * 16;
    const int tid = threadIdx.x;       // 128
    const int nx  = tid & 7;           // handles n = nx*2, nx*2+1
    const int by  = tid >> 3;          // 0..15, batch rows by*4..+3

    const float* hprev = g_hseq + (t > 0 ? (size_t)(t - 1) * B_SZ * H_SZ : 0);

    float acc[4][2][4];
    #pragma unroll
    for (int r = 0; r < 4; r++)
        #pragma unroll
        for (int n = 0; n < 2; n++)
            #pragma unroll
            for (int g = 0; g < 4; g++) acc[r][n][g] = 0.f;

    for (int kc = 0; kc < H_SZ; kc += KC) {
        // h tile 64x32
        for (int idx = tid; idx < 64 * KC; idx += 128) {
            int r = idx >> 5, kk = idx & 31;
            hs[r][kk] = (t == 0) ? 0.f : hprev[(size_t)(b0 + r) * H_SZ + kc + kk];
        }
        // W tile: 4 gates x 16 n x 32 k
        for (int idx = tid; idx < 4 * 16 * KC; idx += 128) {
            int g = idx >> 9;
            int n = (idx >> 5) & 15;
            int kk = idx & 31;
            ws[g][n][kk] = Whh[(size_t)(g * H_SZ + n0 + n) * H_SZ + kc + kk];
        }
        __syncthreads();

        #pragma unroll
        for (int kk = 0; kk < KC; kk++) {
            float a[4];
            #pragma unroll
            for (int r = 0; r < 4; r++) a[r] = hs[by * 4 + r][kk];
            float w[2][4];
            #pragma unroll
            for (int n = 0; n < 2; n++)
                #pragma unroll
                for (int g = 0; g < 4; g++) w[n][g] = ws[g][nx * 2 + n][kk];
            #pragma unroll
            for (int r = 0; r < 4; r++)
                #pragma unroll
                for (int n = 0; n < 2; n++)
                    #pragma unroll
                    for (int g = 0; g < 4; g++) acc[r][n][g] += a[r] * w[n][g];
        }
        __syncthreads();
    }

    // epilogue: LSTM cell + mask
    #pragma unroll
    for (int r = 0; r < 4; r++) {
        const int b = b0 + by * 4 + r;
        const bool valid = (t < lens[b]);
        const float* xg = g_Xg + ((size_t)t * B_SZ + b) * G_SZ;
        #pragma unroll
        for (int n = 0; n < 2; n++) {
            const int hn = n0 + nx * 2 + n;
            float gi = acc[r][n][0] + xg[hn];
            float gf = acc[r][n][1] + xg[256 + hn];
            float gg = acc[r][n][2] + xg[512 + hn];
            float go = acc[r][n][3] + xg[768 + hn];
            float c_old = g_c[b * H_SZ + hn];
            float cn = sigf(gf) * c_old + sigf(gi) * tanhf(gg);
            float hv = sigf(go) * tanhf(cn);
            float h_old = (t == 0) ? 0.f : hprev[(size_t)b * H_SZ + hn];
            float hout = valid ? hv : h_old;
            float cout = valid ? cn : c_old;
            g_c[b * H_SZ + hn] = cout;
            g_hseq[((size_t)t * B_SZ + b) * H_SZ + hn] = hout;
        }
    }
}

// ---------------- scoring ---------------------------------------------------
// S1: E = c_last; E1 = E/max(||E||,1e-12); En = E1/max(||E1||,1e-8)
__global__ void score_norm_kernel() {
    __shared__ float sh[32];
    int b = blockIdx.x, tid = threadIdx.x;
    float e = g_c[b * H_SZ + tid];
    float n1 = sqrtf(block_sum(e * e, sh));
    float e1 = e / fmaxf(n1, 1e-12f);
    float n2 = sqrtf(block_sum(e1 * e1, sh));
    float en = e1 / fmaxf(n2, 1e-8f);
    g_E1[b * H_SZ + tid] = e1;
    g_En[b * H_SZ + tid] = en;
}

// S2: C[i] = mean_j E1[i*M+j]; Cn = normalize(C, eps=1e-8)
__global__ void score_centroid_kernel() {
    __shared__ float sh[32];
    int i = blockIdx.x, tid = threadIdx.x;
    float s = 0.f;
    #pragma unroll
    for (int j = 0; j < M_UTT; j++) s += g_E1[(i * M_UTT + j) * H_SZ + tid];
    float c = s * (1.f / M_UTT);
    float n = sqrtf(block_sum(c * c, sh));
    g_C[i * H_SZ + tid]  = c;
    g_Cn[i * H_SZ + tid] = c / fmaxf(n, 1e-8f);
}

// S3: Cm = (M*C[b/M] + E1[b]) / (M-1); d[b] = dot(En[b], normalize(Cm))
__global__ void score_diag_kernel() {
    __shared__ float sh[32];
    int b = blockIdx.x, tid = threadIdx.x;
    float cm = ((float)M_UTT * g_C[(b / M_UTT) * H_SZ + tid] + g_E1[b * H_SZ + tid])
               * (1.f / (M_UTT - 1));
    float n = sqrtf(block_sum(cm * cm, sh));
    float cmn = cm / fmaxf(n, 1e-8f);
    float d = block_sum(g_En[b * H_SZ + tid] * cmn, sh);
    if (tid == 0) g_d[b] = d;
}

// S4: S[b,i] = w*dot(En[b], Cn[i]) + bias; S[b, b/M] = w*d[b] + bias
__global__ void score_sim_kernel(const float* __restrict__ wsim,
                                 const float* __restrict__ bsim,
                                 float* __restrict__ out)
{
    __shared__ float en[H_SZ];
    int b = blockIdx.x;
    for (int k = threadIdx.x; k < H_SZ; k += 64) en[k] = g_En[b * H_SZ + k];
    __syncthreads();
    int i = threadIdx.x;  // 0..63
    float dot = 0.f;
    #pragma unroll 8
    for (int k = 0; k < H_SZ; k++) dot += en[k] * g_Cn[i * H_SZ + k];
    float w = *wsim, bs = *bsim;
    float val = (i == b / M_UTT) ? g_d[b] : dot;
    out[b * N_SPK + i] = val * w + bs;
}

// ---------------- launch ----------------------------------------------------
extern "C" void kernel_launch(void* const* d_in, const int* in_sizes, int n_in,
                              void* d_out, int out_size)
{
    (void)n_in; (void)out_size;
    const float* seq  = (const float*)d_in[0];
    const int*   lens = (const int*)d_in[1];

    // Input ordering follows setup_inputs() dict insertion order:
    //   0: sequences, 1: len_sequences, 2: w_sim, 3: b_sim,
    //   4..7: Wih0,Whh0,bih0,bhh0, 8..11: layer1, 12..15: layer2
    // Detect defensively via in_sizes (w_sim is a 1-element tensor).
    const float *Wih[3], *Whh[3], *bih[3], *bhh[3], *wsim, *bsim;
    if (in_sizes[2] == 1) {                    // dict order (expected)
        wsim = (const float*)d_in[2];
        bsim = (const float*)d_in[3];
        for (int l = 0; l < 3; l++) {
            Wih[l] = (const float*)d_in[4 + 4 * l];
            Whh[l] = (const float*)d_in[5 + 4 * l];
            bih[l] = (const float*)d_in[6 + 4 * l];
            bhh[l] = (const float*)d_in[7 + 4 * l];
        }
    } else {                                   // signature order (fallback)
        for (int l = 0; l < 3; l++) {
            Wih[l] = (const float*)d_in[2 + 4 * l];
            Whh[l] = (const float*)d_in[3 + 4 * l];
            bih[l] = (const float*)d_in[4 + 4 * l];
            bhh[l] = (const float*)d_in[5 + 4 * l];
        }
        wsim = (const float*)d_in[14];
        bsim = (const float*)d_in[15];
    }
    float* out = (float*)d_out;

    const dim3 bulk_grid(G_SZ / 64, (T_LEN * B_SZ) / 64);   // (16, 1600)
    const dim3 step_grid(H_SZ / 16, B_SZ / 64);             // (16, 10)

    for (int l = 0; l < 3; l++) {
        zero_c_kernel<<<B_SZ, H_SZ>>>();
        int K    = (l == 0) ? IN_F : H_SZ;
        int mode = (l == 0) ? 0 : 1;
        bulk_gemm_kernel<<<bulk_grid, 128>>>(seq, Wih[l], bih[l], bhh[l], K, mode);
        for (int t = 0; t < T_LEN; t++) {
            lstm_step_kernel<<<step_grid, 128>>>(Whh[l], lens, t);
        }
    }

    score_norm_kernel<<<B_SZ, H_SZ>>>();
    score_centroid_kernel<<<N_SPK, H_SZ>>>();
    score_diag_kernel<<<B_SZ, H_SZ>>>();
    score_sim_kernel<<<B_SZ, 64>>>(wsim, bsim, out);
}

// round 6
// speedup vs baseline: 2.0888x; 2.0888x over previous
#include <cuda_runtime.h>
#include <math.h>

#define T_LEN 160
#define B_SZ  640
#define IN_F  40
#define H_SZ  256
#define G_SZ  1024
#define N_SPK 64
#define M_UTT 10
#define KC    32

#define NBT   8        // batch tiles
#define BT    80       // batch rows per block (8*80 = 640)
#define NCT   16       // col tiles (hn tiles)
#define HN_T  16       // hn per block
#define HS_PAD 260     // padded row stride for h tile (256+4, mult of 4)

// ---------------- device scratch (static globals; no runtime alloc) ----------
static __device__ float g_Xg[(size_t)T_LEN * B_SZ * G_SZ];     // precomputed input gates
static __device__ float g_hseq[(size_t)T_LEN * B_SZ * H_SZ];   // h sequence (recurrence exchange buffer)
static __device__ float g_c[B_SZ * H_SZ];                      // final cell state
static __device__ float g_E1[B_SZ * H_SZ];
static __device__ float g_En[B_SZ * H_SZ];
static __device__ float g_C[N_SPK * H_SZ];
static __device__ float g_Cn[N_SPK * H_SZ];
static __device__ float g_d[B_SZ];
static __device__ unsigned int g_bar[NBT];                     // per-btile step barrier

// ---------------- helpers ---------------------------------------------------
__device__ __forceinline__ float block_sum(float v, float* sh) {
    int tid = threadIdx.x;
    #pragma unroll
    for (int o = 16; o > 0; o >>= 1) v += __shfl_down_sync(0xffffffffu, v, o);
    if ((tid & 31) == 0) sh[tid >> 5] = v;
    __syncthreads();
    int nw = blockDim.x >> 5;
    float r = (tid < nw) ? sh[tid] : 0.f;
    if (tid < 32) {
        #pragma unroll
        for (int o = 16; o > 0; o >>= 1) r += __shfl_down_sync(0xffffffffu, r, o);
        if (tid == 0) sh[0] = r;
    }
    __syncthreads();
    float out = sh[0];
    __syncthreads();
    return out;
}

__device__ __forceinline__ float sigf(float x) { return 1.f / (1.f + __expf(-x)); }

__device__ __forceinline__ float f4c(const float4& v, int j) {
    return (j == 0) ? v.x : (j == 1) ? v.y : (j == 2) ? v.z : v.w;
}

// ---------------- barrier reset ---------------------------------------------
__global__ void init_bar_kernel() {
    if (threadIdx.x < NBT) g_bar[threadIdx.x] = 0u;
}

// ---------------- bulk input GEMM: Xg = A @ Wih^T + (bih + bhh) -------------
__global__ void bulk_gemm_kernel(const float* __restrict__ A,
                                 const float* __restrict__ W,
                                 const float* __restrict__ bih,
                                 const float* __restrict__ bhh,
                                 int K, int mode)
{
    __shared__ float As[64][KC + 1];
    __shared__ float Bs[64][KC + 1];

    const int row0 = blockIdx.y * 64;
    const int col0 = blockIdx.x * 64;
    const int tid  = threadIdx.x;          // 128
    const int tx   = tid & 7;
    const int ty   = tid >> 3;

    float acc[4][8];
    #pragma unroll
    for (int r = 0; r < 4; r++)
        #pragma unroll
        for (int c = 0; c < 8; c++) acc[r][c] = 0.f;

    const float* src = (mode == 0) ? A : g_hseq;
    const int nk = (K + KC - 1) / KC;

    for (int kc = 0; kc < nk; kc++) {
        const int kbase = kc * KC;
        for (int idx = tid; idx < 64 * KC; idx += 128) {
            int r = idx >> 5, kk = idx & 31;
            int k = kbase + kk;
            float v = 0.f;
            if (k < K) {
                int row = row0 + r;
                if (mode == 0) {
                    int t = row / B_SZ;
                    int b = row - t * B_SZ;
                    v = src[(size_t)b * (T_LEN * IN_F) + (size_t)t * IN_F + k];
                } else {
                    v = src[(size_t)row * K + k];
                }
            }
            As[r][kk] = v;
        }
        for (int idx = tid; idx < 64 * KC; idx += 128) {
            int r = idx >> 5, kk = idx & 31;
            int k = kbase + kk;
            Bs[r][kk] = (k < K) ? W[(size_t)(col0 + r) * K + k] : 0.f;
        }
        __syncthreads();

        #pragma unroll
        for (int kk = 0; kk < KC; kk++) {
            float a[4], w[8];
            #pragma unroll
            for (int r = 0; r < 4; r++) a[r] = As[ty * 4 + r][kk];
            #pragma unroll
            for (int c = 0; c < 8; c++) w[c] = Bs[tx + c * 8][kk];
            #pragma unroll
            for (int r = 0; r < 4; r++)
                #pragma unroll
                for (int c = 0; c < 8; c++) acc[r][c] += a[r] * w[c];
        }
        __syncthreads();
    }

    #pragma unroll
    for (int r = 0; r < 4; r++) {
        int row = row0 + ty * 4 + r;
        #pragma unroll
        for (int c = 0; c < 8; c++) {
            int col = col0 + tx + c * 8;
            g_Xg[(size_t)row * G_SZ + col] = acc[r][c] + bih[col] + bhh[col];
        }
    }
}

// ---------------- persistent LSTM recurrence (one launch per layer) ----------
// Grid (NCT, NBT) = (16, 8) = 128 blocks, 256 threads each, 1 block/SM.
// Block owns: batch rows [b0, b0+80), hn [n0, n0+16) (x4 gates = 64 gate cols).
// Whh slice (256 K x 16 nx x 4 g = 64KB) resident in SMEM for all 160 steps.
// c and h-carry live in registers. h exchanged via g_hseq + per-btile barrier.
__global__ void __launch_bounds__(256)
lstm_persistent_kernel(const float* __restrict__ Whh,
                       const int* __restrict__ lens)
{
    extern __shared__ float sm[];
    float* ws = sm;                 // [k=256][nx=16][g=4]  = 16384 floats
    float* hs = sm + 16384;         // [b=80][HS_PAD=260]   = 20800 floats

    const int tid = threadIdx.x;    // 256
    const int nx  = tid & 15;       // hn lane
    const int by  = tid >> 4;       // 0..15, batch rows by*5..+4
    const int n0  = blockIdx.x * HN_T;
    const int b0  = blockIdx.y * BT;
    const int hn  = n0 + nx;
    const unsigned bt = blockIdx.y;

    // ---- load W slice into smem (once per layer) ----
    for (int i = 0; i < 64; i++) {
        int lin = tid + i * 256;           // 0..16383
        int k   = lin & 255;
        int col = lin >> 8;                // 0..63
        int wnx = col >> 2;
        int wg  = col & 3;
        ws[(k * 16 + wnx) * 4 + wg] = Whh[(size_t)(wg * H_SZ + n0 + wnx) * H_SZ + k];
    }

    // ---- per-thread state ----
    int   len_r[5];
    float c_r[5], h_r[5];
    #pragma unroll
    for (int r = 0; r < 5; r++) {
        len_r[r] = lens[b0 + by * 5 + r];
        c_r[r] = 0.f;
        h_r[r] = 0.f;
    }

    __syncthreads();   // ws ready

    for (int t = 0; t < T_LEN; t++) {
        // ---- prefetch Xg gate values (independent of h) ----
        float xg[5][4];
        #pragma unroll
        for (int r = 0; r < 5; r++) {
            const float* xrow = g_Xg + ((size_t)t * B_SZ + b0 + by * 5 + r) * G_SZ;
            #pragma unroll
            for (int g = 0; g < 4; g++) xg[r][g] = xrow[g * H_SZ + hn];
        }

        float acc[5][4];
        #pragma unroll
        for (int r = 0; r < 5; r++)
            #pragma unroll
            for (int g = 0; g < 4; g++) acc[r][g] = 0.f;

        if (t > 0) {
            // ---- load h_{t-1} tile [80,256] into smem (float4) ----
            const float* hp = g_hseq + (size_t)(t - 1) * B_SZ * H_SZ;
            #pragma unroll
            for (int i = 0; i < 20; i++) {
                int lin = tid + i * 256;       // 0..5119 float4 slots
                int b   = lin >> 6;            // 0..79
                int kq  = lin & 63;            // float4 index within row
                float4 v = *(const float4*)(hp + (size_t)(b0 + b) * H_SZ + kq * 4);
                *(float4*)&hs[b * HS_PAD + kq * 4] = v;
            }
            __syncthreads();

            // ---- GEMM: acc[r][g] += h[b, k] * W[k, nx, g] ----
            #pragma unroll 4
            for (int kq = 0; kq < 64; kq++) {
                const int k0 = kq * 4;
                float4 a[5];
                #pragma unroll
                for (int r = 0; r < 5; r++)
                    a[r] = *(const float4*)&hs[(by * 5 + r) * HS_PAD + k0];
                #pragma unroll
                for (int j = 0; j < 4; j++) {
                    float4 w = *(const float4*)&ws[((k0 + j) * 16 + nx) * 4];
                    #pragma unroll
                    for (int r = 0; r < 5; r++) {
                        float av = f4c(a[r], j);
                        acc[r][0] += av * w.x;
                        acc[r][1] += av * w.y;
                        acc[r][2] += av * w.z;
                        acc[r][3] += av * w.w;
                    }
                }
            }
        }

        // ---- LSTM cell + mask, write h ----
        float* hout_base = g_hseq + (size_t)t * B_SZ * H_SZ;
        #pragma unroll
        for (int r = 0; r < 5; r++) {
            const int b = b0 + by * 5 + r;
            const bool valid = (t < len_r[r]);
            float gi = acc[r][0] + xg[r][0];
            float gf = acc[r][1] + xg[r][1];
            float gg = acc[r][2] + xg[r][2];
            float go = acc[r][3] + xg[r][3];
            float cn = sigf(gf) * c_r[r] + sigf(gi) * tanhf(gg);
            float hv = sigf(go) * tanhf(cn);
            float ho = valid ? hv : h_r[r];
            float co = valid ? cn : c_r[r];
            c_r[r] = co;
            h_r[r] = ho;
            hout_base[(size_t)b * H_SZ + hn] = ho;
        }

        // ---- per-btile barrier (16 col-blocks) ----
        if (t < T_LEN - 1) {
            __threadfence();
            __syncthreads();
            if (tid == 0) {
                atomicAdd(&g_bar[bt], 1u);
                const unsigned target = (unsigned)(NCT * (t + 1));
                while (*(volatile unsigned int*)&g_bar[bt] < target) __nanosleep(64);
                __threadfence();
            }
            __syncthreads();
        }
    }

    // ---- write final cell state ----
    #pragma unroll
    for (int r = 0; r < 5; r++)
        g_c[(size_t)(b0 + by * 5 + r) * H_SZ + hn] = c_r[r];
}

// ---------------- scoring ---------------------------------------------------
__global__ void score_norm_kernel() {
    __shared__ float sh[32];
    int b = blockIdx.x, tid = threadIdx.x;
    float e = g_c[b * H_SZ + tid];
    float n1 = sqrtf(block_sum(e * e, sh));
    float e1 = e / fmaxf(n1, 1e-12f);
    float n2 = sqrtf(block_sum(e1 * e1, sh));
    float en = e1 / fmaxf(n2, 1e-8f);
    g_E1[b * H_SZ + tid] = e1;
    g_En[b * H_SZ + tid] = en;
}

__global__ void score_centroid_kernel() {
    __shared__ float sh[32];
    int i = blockIdx.x, tid = threadIdx.x;
    float s = 0.f;
    #pragma unroll
    for (int j = 0; j < M_UTT; j++) s += g_E1[(i * M_UTT + j) * H_SZ + tid];
    float c = s * (1.f / M_UTT);
    float n = sqrtf(block_sum(c * c, sh));
    g_C[i * H_SZ + tid]  = c;
    g_Cn[i * H_SZ + tid] = c / fmaxf(n, 1e-8f);
}

__global__ void score_diag_kernel() {
    __shared__ float sh[32];
    int b = blockIdx.x, tid = threadIdx.x;
    float cm = ((float)M_UTT * g_C[(b / M_UTT) * H_SZ + tid] + g_E1[b * H_SZ + tid])
               * (1.f / (M_UTT - 1));
    float n = sqrtf(block_sum(cm * cm, sh));
    float cmn = cm / fmaxf(n, 1e-8f);
    float d = block_sum(g_En[b * H_SZ + tid] * cmn, sh);
    if (tid == 0) g_d[b] = d;
}

__global__ void score_sim_kernel(const float* __restrict__ wsim,
                                 const float* __restrict__ bsim,
                                 float* __restrict__ out)
{
    __shared__ float en[H_SZ];
    int b = blockIdx.x;
    for (int k = threadIdx.x; k < H_SZ; k += 64) en[k] = g_En[b * H_SZ + k];
    __syncthreads();
    int i = threadIdx.x;  // 0..63
    float dot = 0.f;
    #pragma unroll 8
    for (int k = 0; k < H_SZ; k++) dot += en[k] * g_Cn[i * H_SZ + k];
    float w = *wsim, bs = *bsim;
    float val = (i == b / M_UTT) ? g_d[b] : dot;
    out[b * N_SPK + i] = val * w + bs;
}

// ---------------- launch ----------------------------------------------------
extern "C" void kernel_launch(void* const* d_in, const int* in_sizes, int n_in,
                              void* d_out, int out_size)
{
    (void)n_in; (void)out_size;
    const float* seq  = (const float*)d_in[0];
    const int*   lens = (const int*)d_in[1];

    // Input ordering: setup_inputs() dict insertion order:
    //   0: sequences, 1: len_sequences, 2: w_sim, 3: b_sim, 4..: per-layer W/b
    const float *Wih[3], *Whh[3], *bih[3], *bhh[3], *wsim, *bsim;
    if (in_sizes[2] == 1) {
        wsim = (const float*)d_in[2];
        bsim = (const float*)d_in[3];
        for (int l = 0; l < 3; l++) {
            Wih[l] = (const float*)d_in[4 + 4 * l];
            Whh[l] = (const float*)d_in[5 + 4 * l];
            bih[l] = (const float*)d_in[6 + 4 * l];
            bhh[l] = (const float*)d_in[7 + 4 * l];
        }
    } else {
        for (int l = 0; l < 3; l++) {
            Wih[l] = (const float*)d_in[2 + 4 * l];
            Whh[l] = (const float*)d_in[3 + 4 * l];
            bih[l] = (const float*)d_in[4 + 4 * l];
            bhh[l] = (const float*)d_in[5 + 4 * l];
        }
        wsim = (const float*)d_in[14];
        bsim = (const float*)d_in[15];
    }
    float* out = (float*)d_out;

    const int smem_bytes = (16384 + BT * HS_PAD) * sizeof(float);  // ~148.7 KB
    cudaFuncSetAttribute(lstm_persistent_kernel,
                         cudaFuncAttributeMaxDynamicSharedMemorySize, smem_bytes);

    const dim3 bulk_grid(G_SZ / 64, (T_LEN * B_SZ) / 64);   // (16, 1600)
    const dim3 pers_grid(NCT, NBT);                          // (16, 8) = 128 blocks

    for (int l = 0; l < 3; l++) {
        int K    = (l == 0) ? IN_F : H_SZ;
        int mode = (l == 0) ? 0 : 1;
        bulk_gemm_kernel<<<bulk_grid, 128>>>(seq, Wih[l], bih[l], bhh[l], K, mode);
        init_bar_kernel<<<1, 32>>>();
        lstm_persistent_kernel<<<pers_grid, 256, smem_bytes>>>(Whh[l], lens);
    }

    score_norm_kernel<<<B_SZ, H_SZ>>>();
    score_centroid_kernel<<<N_SPK, H_SZ>>>();
    score_diag_kernel<<<B_SZ, H_SZ>>>();
    score_sim_kernel<<<B_SZ, 64>>>(wsim, bsim, out);
}